// round 16
// baseline (speedup 1.0000x reference)
#include <cuda_runtime.h>
#include <cuda_fp16.h>
#include <cstdint>

#define BB 2
#define TT 2048
#define DD 1024
#define HH 16
#define HD 64
#define BTD ((size_t)BB*TT*DD)

// ---- scratch (device globals: allocation-free) ----
__device__ __half g_ln  [BTD];
__device__ __half g_qkv [3 * BTD];                 // q,k,v [B,H,T,hd] fp16 (q pre-scaled by 0.125)
__device__ __half g_ctx [BTD];                     // [B,T,D] fp16
__device__ float  g_h   [BTD];                     // block-1 output (fp32)
__device__ __half g_w   [4][(size_t)DD*DD];        // wq,wk,wv,wo fp16 (qkv rows contiguous)

// ===========================================================================
// helpers
// ===========================================================================
__device__ __forceinline__ void mma16(float* c, const uint32_t* a, const uint32_t* b) {
    asm volatile(
        "mma.sync.aligned.m16n8k16.row.col.f32.f16.f16.f32 "
        "{%0,%1,%2,%3}, {%4,%5,%6,%7}, {%8,%9}, {%0,%1,%2,%3};"
        : "+f"(c[0]), "+f"(c[1]), "+f"(c[2]), "+f"(c[3])
        : "r"(a[0]), "r"(a[1]), "r"(a[2]), "r"(a[3]), "r"(b[0]), "r"(b[1]));
}
__device__ __forceinline__ void ldsm4(uint32_t& r0, uint32_t& r1,
                                      uint32_t& r2, uint32_t& r3, uint32_t addr) {
    asm volatile("ldmatrix.sync.aligned.m8n8.x4.shared.b16 {%0,%1,%2,%3}, [%4];"
        : "=r"(r0), "=r"(r1), "=r"(r2), "=r"(r3) : "r"(addr));
}
__device__ __forceinline__ void ldsm4t(uint32_t& r0, uint32_t& r1,
                                       uint32_t& r2, uint32_t& r3, uint32_t addr) {
    asm volatile("ldmatrix.sync.aligned.m8n8.x4.trans.shared.b16 {%0,%1,%2,%3}, [%4];"
        : "=r"(r0), "=r"(r1), "=r"(r2), "=r"(r3) : "r"(addr));
}
__device__ __forceinline__ uint32_t s2u(const void* p) {
    return (uint32_t)__cvta_generic_to_shared(p);
}
__device__ __forceinline__ uint32_t packh2(float lo, float hi) {
    __half2 h = __floats2half2_rn(lo, hi);
    return *(uint32_t*)&h;
}
__device__ __forceinline__ uint32_t ex2h2(uint32_t x) {   // paired fp16 exp2
    uint32_t r;
    asm("ex2.approx.f16x2 %0, %1;" : "=r"(r) : "r"(x));
    return r;
}
__device__ __forceinline__ uint32_t hmax2u(uint32_t a, uint32_t b) {
    __half2 r = __hmax2(*(__half2*)&a, *(__half2*)&b);
    return *(uint32_t*)&r;
}
__device__ __forceinline__ void cpa16(uint32_t dst, const void* src) {
    asm volatile("cp.async.ca.shared.global [%0], [%1], 16;" :: "r"(dst), "l"(src));
}
__device__ __forceinline__ void cp_commit() {
    asm volatile("cp.async.commit_group;" ::: "memory");
}
template <int N>
__device__ __forceinline__ void cp_wait() {
    asm volatile("cp.async.wait_group %0;" :: "n"(N) : "memory");
}

#define KP   72          // flash K/V row stride (halves); 144B rows
#define VP   72
#define GP   72          // dense BK=64 row stride (halves); 144B rows
#define FULL 0xffffffffu
#define ASTB (128 * GP * 2)     // dense A per-stage bytes (18432)
#define BSTB (64 * GP * 2)      // dense B per-stage bytes (9216)
#define GSMEM (2 * ASTB + 2 * BSTB)   // 55296 B dense dynamic smem
#define KSTG (64 * KP * 2)      // flash K/V stage bytes
#define L2E  1.4426950408889634f
#define ONE2 0x3C003C00u        // half2(1.0, 1.0)

// ===========================================================================
// weight converter: fp32 -> fp16, all 4 matrices in one launch
// ===========================================================================
__global__ void cvt_h4(const float4* __restrict__ w0, const float4* __restrict__ w1,
                       const float4* __restrict__ w2, const float4* __restrict__ w3,
                       __half2* __restrict__ out) {
    int m = blockIdx.y;
    const float4* in = (m == 0) ? w0 : (m == 1) ? w1 : (m == 2) ? w2 : w3;
    size_t base = (size_t)m * (DD * DD / 2);
    int i = blockIdx.x * 256 + threadIdx.x;
    float4 v = in[i];
    out[base + 2 * i]     = __floats2half2_rn(v.x, v.y);
    out[base + 2 * i + 1] = __floats2half2_rn(v.z, v.w);
}

// ===========================================================================
// Dense GEMM: C[4096, N] = A[4096,1024] @ W[N,1024]^T, fp16 in, fp32 accum.
// BM=128, BN=64, BK=64. 128 threads = 4 warps in 2(M)x2(N); warp tile 64x32
// (identical per-warp structure to the previous 256-thread version).
// 4 CTAs/SM residency (regs capped at 128, smem 55.3 KB).
// cp.async 2-stage, single barrier per 64-wide k-tile, m16n8k16 + ldmatrix.
//   MODE 0 (N=3072, fused QKV): emit fp16 into g_qkv; q part scaled by 0.125
//   MODE 1 (N=1024, out-proj):  fp32 out = res + bias + C
// smem layout (bytes): A[st0], A[st1] (ASTB each), B[st0], B[st1] (BSTB each)
// ===========================================================================
template <int MODE>
__global__ __launch_bounds__(128, 4)
void mma_gemm(const __half* __restrict__ A, const __half* __restrict__ W,
              const float* __restrict__ bias, const float* __restrict__ res,
              void* __restrict__ outv) {
    extern __shared__ __align__(16) __half dsm[];
    uint32_t base = s2u(dsm);
    const uint32_t BOFF = 2 * ASTB;
    int tid = threadIdx.x, lane = tid & 31, warp = tid >> 5;
    int wm = (warp >> 1) * 64, wn = (warp & 1) * 32;
    int g = lane >> 2, t = lane & 3;
    int m0 = blockIdx.y * 128, n0 = blockIdx.x * 64;

    // cp.async: 16 rows x 64 halves per pass; A = 8 passes, B = 4 passes
    int lrow = tid >> 3, lc8 = (tid & 7) * 8;
    const __half* Ag = A + (size_t)(m0 + lrow) * DD + lc8;
    const __half* Wg = W + (size_t)(n0 + lrow) * DD + lc8;
    uint32_t aS = base + (lrow * GP + lc8) * 2;
    uint32_t bS = base + BOFF + (lrow * GP + lc8) * 2;
    const uint32_t RG = 16 * GP * 2;
    const size_t   RGg = (size_t)16 * DD;

    int lr = lane & 15, lch = (lane >> 4) * 8;
    int brow = (lane & 7) + ((lane & 16) >> 1);
    int bch = (lane & 8);
    uint32_t aA[4], bA[2];
#pragma unroll
    for (int i = 0; i < 4; i++)
        aA[i] = base + ((wm + i * 16 + lr) * GP + lch) * 2;
#pragma unroll
    for (int jp = 0; jp < 2; jp++)
        bA[jp] = base + BOFF + ((wn + jp * 16 + brow) * GP + bch) * 2;

    float acc[4][4][4] = {};

    // prologue: stage 0 <- k-tile 0
#pragma unroll
    for (int p = 0; p < 8; p++) cpa16(aS + p * RG, Ag + p * RGg);
#pragma unroll
    for (int p = 0; p < 4; p++) cpa16(bS + p * RG, Wg + p * RGg);
    cp_commit();

    const int NKT = DD / 64;
    for (int kt = 0; kt < NKT; kt++) {
        cp_wait<0>();
        __syncthreads();        // publishes tile kt; retires reads of stage kt^1
        if (kt + 1 < NKT) {
            int k0 = (kt + 1) * 64;
            uint32_t spa = ((kt + 1) & 1) * (uint32_t)ASTB;
            uint32_t spb = ((kt + 1) & 1) * (uint32_t)BSTB;
#pragma unroll
            for (int p = 0; p < 8; p++) cpa16(aS + spa + p * RG, Ag + p * RGg + k0);
#pragma unroll
            for (int p = 0; p < 4; p++) cpa16(bS + spb + p * RG, Wg + p * RGg + k0);
            cp_commit();
        }
        uint32_t soa = (kt & 1) * (uint32_t)ASTB;
        uint32_t sob = (kt & 1) * (uint32_t)BSTB;
#pragma unroll
        for (int kk = 0; kk < 4; kk++) {
            int ko = kk * 32;
            uint32_t af[4][4], bf[4][2];
#pragma unroll
            for (int i = 0; i < 4; i++)
                ldsm4(af[i][0], af[i][1], af[i][2], af[i][3], aA[i] + soa + ko);
#pragma unroll
            for (int jp = 0; jp < 2; jp++)
                ldsm4(bf[2*jp][0], bf[2*jp][1], bf[2*jp+1][0], bf[2*jp+1][1],
                      bA[jp] + sob + ko);
#pragma unroll
            for (int i = 0; i < 4; i++)
#pragma unroll
                for (int j = 0; j < 4; j++)
                    mma16(acc[i][j], af[i], bf[j]);
        }
    }

    if (MODE == 0) {
        __half* out = (__half*)outv + (size_t)(n0 >> 10) * BTD;   // q/k/v select
        float qs = (n0 < DD) ? 0.125f : 1.f;                      // fold 1/sqrt(hd) into Q
#pragma unroll
        for (int i = 0; i < 4; i++) {
            int row = m0 + wm + i * 16 + g;
            int b = row >> 11, tt = row & 2047;
#pragma unroll
            for (int j = 0; j < 4; j++) {
                int col = (n0 & 1023) + wn + j * 8 + 2 * t;
                int h = col >> 6, d = col & 63;
                __half* d0 = out + (((size_t)(b * HH + h)) * TT + tt) * HD + d;
                __half* d1 = out + (((size_t)(b * HH + h)) * TT + tt + 8) * HD + d;
                *(__half2*)d0 = __floats2half2_rn(acc[i][j][0] * qs, acc[i][j][1] * qs);
                *(__half2*)d1 = __floats2half2_rn(acc[i][j][2] * qs, acc[i][j][3] * qs);
            }
        }
    } else {
        float* out = (float*)outv;
#pragma unroll
        for (int i = 0; i < 4; i++) {
            int row = m0 + wm + i * 16 + g;
#pragma unroll
            for (int j = 0; j < 4; j++) {
                int col = n0 + wn + j * 8 + 2 * t;
                float2 b2 = *(const float2*)(bias + col);
                float2 r0 = *(const float2*)(res + (size_t)row * DD + col);
                float2 r1 = *(const float2*)(res + (size_t)(row + 8) * DD + col);
                *(float2*)(out + (size_t)row * DD + col) =
                    make_float2(acc[i][j][0] + r0.x + b2.x, acc[i][j][1] + r0.y + b2.y);
                *(float2*)(out + (size_t)(row + 8) * DD + col) =
                    make_float2(acc[i][j][2] + r1.x + b2.x, acc[i][j][3] + r1.y + b2.y);
            }
        }
    }
}

// ===========================================================================
// Fused flash attention (fp16 in/out, fp32 accum). Q pre-scaled by 0.125.
// 64 q-rows per CTA, 128 threads (4 warps x 16 rows), static smem, 2-stage
// cp.async, single barrier per kv-tile. Grid (bh, tile) with tiles reversed
// (all bh instances of the heaviest tile launch first). Maskless mainloop;
// diagonal tile is the final iteration.
// ===========================================================================
__global__ __launch_bounds__(128, 4)
void flash_attn(const __half* __restrict__ Q, const __half* __restrict__ K,
                const __half* __restrict__ V, __half* __restrict__ C) {
    __shared__ __align__(16) __half Ks[2][64 * KP];
    __shared__ __align__(16) __half Vs[2][64 * VP];

    int bh = blockIdx.x;                            // x = bh (fast dim)
    int m0 = (gridDim.y - 1 - blockIdx.y) * 64;     // y = q-tile, heaviest first
    const __half* Qb = Q + (size_t)bh * TT * HD;
    const __half* Kb = K + (size_t)bh * TT * HD;
    const __half* Vb = V + (size_t)bh * TT * HD;

    int tid = threadIdx.x, lane = tid & 31, warp = tid >> 5;
    int wm = warp * 16;
    int g = lane >> 2, t = lane & 3;
    int row0 = m0 + wm + g, row1 = row0 + 8;

    int lrow = tid >> 3, lc8 = (tid & 7) * 8;
    const __half* Kg = Kb + (size_t)lrow * HD + lc8;
    const __half* Vg = Vb + (size_t)lrow * HD + lc8;
    uint32_t kS = s2u(Ks) + (lrow * KP + lc8) * 2;
    uint32_t vS = s2u(Vs) + (lrow * VP + lc8) * 2;
    const uint32_t RGK = 16 * KP * 2, RGV = 16 * VP * 2;
    const size_t RGg = (size_t)16 * HD;

    uint32_t ksb = s2u(Ks), vsb = s2u(Vs);
    int krow = (lane & 7) + ((lane & 16) >> 1);
    int kch = (lane & 8);
    uint32_t kA[4];
#pragma unroll
    for (int jp = 0; jp < 4; jp++)
        kA[jp] = ksb + ((jp * 16 + krow) * KP + kch) * 2;
    uint32_t vA = vsb + (((lane & 7) + (lane & 8)) * VP + ((lane & 16) >> 1)) * 2;

    uint32_t qf[4][4];
#pragma unroll
    for (int ks = 0; ks < 4; ks++) {
        int kb = ks * 16;
        qf[ks][0] = *(const uint32_t*)(Qb + (size_t)row0 * HD + kb + 2 * t);
        qf[ks][1] = *(const uint32_t*)(Qb + (size_t)row1 * HD + kb + 2 * t);
        qf[ks][2] = *(const uint32_t*)(Qb + (size_t)row0 * HD + kb + 8 + 2 * t);
        qf[ks][3] = *(const uint32_t*)(Qb + (size_t)row1 * HD + kb + 8 + 2 * t);
    }

    float o[8][4] = {};
    float sacc[4] = {};
    float rmax0 = -1e30f, rmax1 = -1e30f;
    const uint32_t onef[2] = {ONE2, ONE2};

    int nkv = (m0 + 64) / 64;
#pragma unroll
    for (int rg = 0; rg < 4; rg++) {
        cpa16(kS + rg * RGK, Kg + rg * RGg);
        cpa16(vS + rg * RGV, Vg + rg * RGg);
    }
    cp_commit();

    for (int kv = 0; kv < nkv; kv++) {
        cp_wait<0>();
        __syncthreads();
        if (kv + 1 < nkv) {
            size_t go = (size_t)(kv + 1) * 64 * HD;
            uint32_t sk = ((kv + 1) & 1) * (uint32_t)KSTG;
#pragma unroll
            for (int rg = 0; rg < 4; rg++) {
                cpa16(kS + sk + rg * RGK, Kg + go + rg * RGg);
                cpa16(vS + sk + rg * RGV, Vg + go + rg * RGg);
            }
            cp_commit();
        }
        uint32_t so = (kv & 1) * (uint32_t)KSTG;

        // ---- S = Q @ K^T (16 x 64) ----
        float s[8][4];
#pragma unroll
        for (int j = 0; j < 8; j++) { s[j][0]=0.f; s[j][1]=0.f; s[j][2]=0.f; s[j][3]=0.f; }
#pragma unroll
        for (int ks = 0; ks < 4; ks++) {
            int ko = ks * 32;
            uint32_t kf[8][2];
#pragma unroll
            for (int jp = 0; jp < 4; jp++)
                ldsm4(kf[2*jp][0], kf[2*jp][1], kf[2*jp+1][0], kf[2*jp+1][1],
                      kA[jp] + so + ko);
#pragma unroll
            for (int j = 0; j < 8; j++)
                mma16(s[j], qf[ks], kf[j]);
        }

        // ---- causal mask: only the diagonal (last) tile ----
        if (kv == nkv - 1) {
            int kv0 = kv * 64;
#pragma unroll
            for (int j = 0; j < 8; j++) {
                int c0 = kv0 + j * 8 + 2 * t, c1 = c0 + 1;
                if (c0 > row0) s[j][0] = -1e30f;
                if (c1 > row0) s[j][1] = -1e30f;
                if (c0 > row1) s[j][2] = -1e30f;
                if (c1 > row1) s[j][3] = -1e30f;
            }
        }

        // ---- online softmax: packed half2 quad max (2 shuffles) ----
        float m0l = -1e30f, m1l = -1e30f;
#pragma unroll
        for (int j = 0; j < 8; j++) {
            m0l = fmaxf(m0l, fmaxf(s[j][0], s[j][1]));
            m1l = fmaxf(m1l, fmaxf(s[j][2], s[j][3]));
        }
        uint32_t pm = packh2(m0l, m1l);
        pm = hmax2u(pm, __shfl_xor_sync(FULL, pm, 1));
        pm = hmax2u(pm, __shfl_xor_sync(FULL, pm, 2));
        __half2 mh = *(__half2*)&pm;
        float mf0 = __low2float(mh), mf1 = __high2float(mh);
        float mn0 = fmaxf(rmax0, mf0), mn1 = fmaxf(rmax1, mf1);
        if (mf0 > rmax0 || mf1 > rmax1) {
            float cr0 = __expf(rmax0 - mn0), cr1 = __expf(rmax1 - mn1);
            sacc[0] *= cr0; sacc[1] *= cr0; sacc[2] *= cr1; sacc[3] *= cr1;
#pragma unroll
            for (int j = 0; j < 8; j++) {
                o[j][0] *= cr0; o[j][1] *= cr0; o[j][2] *= cr1; o[j][3] *= cr1;
            }
        }
        rmax0 = mn0; rmax1 = mn1;

        // ---- exp (log2 domain, paired fp16) -> P frags ----
        float b0 = -mn0 * L2E, b1 = -mn1 * L2E;
        uint32_t pan[4][4];
#pragma unroll
        for (int kb2 = 0; kb2 < 4; kb2++) {
            int j0 = 2 * kb2, j1 = 2 * kb2 + 1;
            pan[kb2][0] = ex2h2(packh2(fmaf(s[j0][0], L2E, b0), fmaf(s[j0][1], L2E, b0)));
            pan[kb2][1] = ex2h2(packh2(fmaf(s[j0][2], L2E, b1), fmaf(s[j0][3], L2E, b1)));
            pan[kb2][2] = ex2h2(packh2(fmaf(s[j1][0], L2E, b0), fmaf(s[j1][1], L2E, b0)));
            pan[kb2][3] = ex2h2(packh2(fmaf(s[j1][2], L2E, b1), fmaf(s[j1][3], L2E, b1)));
        }

        // ---- row sums (ones-mma) + O += P @ V ----
#pragma unroll
        for (int kb2 = 0; kb2 < 4; kb2++) {
            mma16(sacc, pan[kb2], onef);
            uint32_t vf[8][2];
#pragma unroll
            for (int jp = 0; jp < 4; jp++)
                ldsm4t(vf[2*jp][0], vf[2*jp][1], vf[2*jp+1][0], vf[2*jp+1][1],
                       vA + so + (kb2 * 16 * VP + jp * 16) * 2);
#pragma unroll
            for (int j = 0; j < 8; j++)
                mma16(o[j], pan[kb2], vf[j]);
        }
    }

    // ---- epilogue ----
    float i0 = 1.f / sacc[0], i1 = 1.f / sacc[2];
    int b = bh >> 4, h = bh & 15;
#pragma unroll
    for (int j = 0; j < 8; j++) {
        int col = j * 8 + 2 * t;
        *(__half2*)(C + ((size_t)(b * TT + row0)) * DD + h * HD + col) =
            __floats2half2_rn(o[j][0] * i0, o[j][1] * i0);
        *(__half2*)(C + ((size_t)(b * TT + row1)) * DD + h * HD + col) =
            __floats2half2_rn(o[j][2] * i1, o[j][3] * i1);
    }
}

// ---------------------------------------------------------------------------
// LayerNorm (faithful bug: scale * x_norm + scale), emits fp16
// ---------------------------------------------------------------------------
__global__ void ln_kernel(const float* __restrict__ x,
                          const float* __restrict__ scale,
                          __half* __restrict__ y) {
    int row = blockIdx.x;
    const float* xr = x + (size_t)row * DD;
    __half* yr = y + (size_t)row * DD;
    int tid = threadIdx.x;
    float v[4];
    float s = 0.f, s2 = 0.f;
#pragma unroll
    for (int i = 0; i < 4; i++) {
        v[i] = xr[tid + 256 * i];
        s  += v[i];
        s2 += v[i] * v[i];
    }
    __shared__ float sh[256], sh2[256];
    sh[tid] = s; sh2[tid] = s2;
    __syncthreads();
    for (int o = 128; o > 0; o >>= 1) {
        if (tid < o) { sh[tid] += sh[tid + o]; sh2[tid] += sh2[tid + o]; }
        __syncthreads();
    }
    float mean = sh[0] * (1.f / DD);
    float var  = sh2[0] * (1.f / DD) - mean * mean;
    float rstd = rsqrtf(var + 1e-5f);
#pragma unroll
    for (int i = 0; i < 4; i++) {
        int c = tid + 256 * i;
        float sc = scale[c];
        yr[c] = __float2half(sc * ((v[i] - mean) * rstd) + sc);
    }
}

// ---------------------------------------------------------------------------
// Host driver
// ---------------------------------------------------------------------------
static void run_block(const float* x_in, const float* ln_scale,
                      const __half* wqkv, const __half* wo, const float* bo,
                      __half* lnp, __half* qkvp, __half* ctxp, float* out) {
    ln_kernel<<<BB * TT, 256>>>(x_in, ln_scale, lnp);
    mma_gemm<0><<<dim3(3 * DD / 64, (BB * TT) / 128), 128, GSMEM>>>(
        lnp, wqkv, nullptr, nullptr, qkvp);
    flash_attn<<<dim3(BB * HH, TT / 64), 128>>>(
        qkvp, qkvp + BTD, qkvp + 2 * BTD, ctxp);
    mma_gemm<1><<<dim3(DD / 64, (BB * TT) / 128), 128, GSMEM>>>(
        ctxp, wo, bo, x_in, out);
}

extern "C" void kernel_launch(void* const* d_in, const int* in_sizes, int n_in,
                              void* d_out, int out_size) {
    const float* x   = (const float*)d_in[0];
    const float* bo  = (const float*)d_in[5];
    const float* ln1 = (const float*)d_in[6];
    const float* ln2 = (const float*)d_in[7];
    float* out = (float*)d_out;

    static bool attr_set = false;
    if (!attr_set) {
        cudaFuncSetAttribute(mma_gemm<0>, cudaFuncAttributeMaxDynamicSharedMemorySize, GSMEM);
        cudaFuncSetAttribute(mma_gemm<1>, cudaFuncAttributeMaxDynamicSharedMemorySize, GSMEM);
        attr_set = true;
    }

    __half *lnp, *qkvp, *ctxp, *wt;
    float* hp;
    cudaGetSymbolAddress((void**)&lnp,  g_ln);
    cudaGetSymbolAddress((void**)&qkvp, g_qkv);
    cudaGetSymbolAddress((void**)&ctxp, g_ctx);
    cudaGetSymbolAddress((void**)&hp,   g_h);
    cudaGetSymbolAddress((void**)&wt,   g_w);

    cvt_h4<<<dim3((DD * DD / 4) / 256, 4), 256>>>(
        (const float4*)d_in[1], (const float4*)d_in[2],
        (const float4*)d_in[3], (const float4*)d_in[4], (__half2*)wt);
    const __half* wqkv = wt;
    const __half* wo   = wt + (size_t)3 * DD * DD;

    run_block(x,  ln1, wqkv, wo, bo, lnp, qkvp, ctxp, hp);
    run_block(hp, ln2, wqkv, wo, bo, lnp, qkvp, ctxp, out);
}

// round 17
// speedup vs baseline: 1.0423x; 1.0423x over previous
#include <cuda_runtime.h>
#include <cuda_fp16.h>
#include <cstdint>

#define BB 2
#define TT 2048
#define DD 1024
#define HH 16
#define HD 64
#define BTD ((size_t)BB*TT*DD)

// ---- scratch (device globals: allocation-free) ----
__device__ __half g_ln  [BTD];
__device__ __half g_qkv [3 * BTD];                 // q,k,v [B,H,T,hd] fp16 (q pre-scaled by 0.125)
__device__ __half g_ctx [BTD];                     // [B,T,D] fp16
__device__ float  g_h   [BTD];                     // block-1 output (fp32)
__device__ __half g_w   [4][(size_t)DD*DD];        // wq,wk,wv,wo fp16 (qkv rows contiguous)

// ===========================================================================
// helpers
// ===========================================================================
__device__ __forceinline__ void mma16(float* c, const uint32_t* a, const uint32_t* b) {
    asm volatile(
        "mma.sync.aligned.m16n8k16.row.col.f32.f16.f16.f32 "
        "{%0,%1,%2,%3}, {%4,%5,%6,%7}, {%8,%9}, {%0,%1,%2,%3};"
        : "+f"(c[0]), "+f"(c[1]), "+f"(c[2]), "+f"(c[3])
        : "r"(a[0]), "r"(a[1]), "r"(a[2]), "r"(a[3]), "r"(b[0]), "r"(b[1]));
}
__device__ __forceinline__ void ldsm4(uint32_t& r0, uint32_t& r1,
                                      uint32_t& r2, uint32_t& r3, uint32_t addr) {
    asm volatile("ldmatrix.sync.aligned.m8n8.x4.shared.b16 {%0,%1,%2,%3}, [%4];"
        : "=r"(r0), "=r"(r1), "=r"(r2), "=r"(r3) : "r"(addr));
}
__device__ __forceinline__ void ldsm4t(uint32_t& r0, uint32_t& r1,
                                       uint32_t& r2, uint32_t& r3, uint32_t addr) {
    asm volatile("ldmatrix.sync.aligned.m8n8.x4.trans.shared.b16 {%0,%1,%2,%3}, [%4];"
        : "=r"(r0), "=r"(r1), "=r"(r2), "=r"(r3) : "r"(addr));
}
__device__ __forceinline__ uint32_t s2u(const void* p) {
    return (uint32_t)__cvta_generic_to_shared(p);
}
__device__ __forceinline__ uint32_t packh2(float lo, float hi) {
    __half2 h = __floats2half2_rn(lo, hi);
    return *(uint32_t*)&h;
}
__device__ __forceinline__ uint32_t ex2h2(uint32_t x) {   // paired fp16 exp2
    uint32_t r;
    asm("ex2.approx.f16x2 %0, %1;" : "=r"(r) : "r"(x));
    return r;
}
__device__ __forceinline__ uint32_t hmax2u(uint32_t a, uint32_t b) {
    __half2 r = __hmax2(*(__half2*)&a, *(__half2*)&b);
    return *(uint32_t*)&r;
}
__device__ __forceinline__ void cpa16(uint32_t dst, const void* src) {
    asm volatile("cp.async.ca.shared.global [%0], [%1], 16;" :: "r"(dst), "l"(src));
}
__device__ __forceinline__ void cp_commit() {
    asm volatile("cp.async.commit_group;" ::: "memory");
}
template <int N>
__device__ __forceinline__ void cp_wait() {
    asm volatile("cp.async.wait_group %0;" :: "n"(N) : "memory");
}

#define KP   72          // flash K/V row stride (halves); 144B rows
#define VP   72
#define GP   72          // dense BK=64 row stride (halves); 144B rows
#define FULL 0xffffffffu
#define ASTB (128 * GP * 2)     // dense per-matrix per-stage bytes (18432)
#define GSMEM (4 * ASTB)        // dense dynamic smem: 2 stages x (A+B) = 73728
#define KSTG (64 * KP * 2)      // flash K/V stage bytes
#define L2E  1.4426950408889634f
#define ONE2 0x3C003C00u        // half2(1.0, 1.0)

// ===========================================================================
// weight converter: fp32 -> fp16, all 4 matrices in one launch
// ===========================================================================
__global__ void cvt_h4(const float4* __restrict__ w0, const float4* __restrict__ w1,
                       const float4* __restrict__ w2, const float4* __restrict__ w3,
                       __half2* __restrict__ out) {
    int m = blockIdx.y;
    const float4* in = (m == 0) ? w0 : (m == 1) ? w1 : (m == 2) ? w2 : w3;
    size_t base = (size_t)m * (DD * DD / 2);
    int i = blockIdx.x * 256 + threadIdx.x;
    float4 v = in[i];
    out[base + 2 * i]     = __floats2half2_rn(v.x, v.y);
    out[base + 2 * i + 1] = __floats2half2_rn(v.z, v.w);
}

// ===========================================================================
// Dense GEMM: C[4096, N] = A[4096,1024] @ W[N,1024]^T, fp16 in, fp32 accum.
// BM=BN=128, BK=64, 8 warps 2x4, warp tile 64x32, m16n8k16, ldmatrix,
// cp.async 2-stage (dynamic smem), SINGLE barrier per 64-wide k-tile.
//   MODE 0 (N=3072, fused QKV): emit fp16 into g_qkv; q part scaled by 0.125
//   MODE 1 (N=1024, out-proj):  fp32 out = res + bias + C
// ===========================================================================
template <int MODE>
__global__ __launch_bounds__(256)
void mma_gemm(const __half* __restrict__ A, const __half* __restrict__ W,
              const float* __restrict__ bias, const float* __restrict__ res,
              void* __restrict__ outv) {
    extern __shared__ __align__(16) __half dsm[];
    uint32_t base = s2u(dsm);
    int tid = threadIdx.x, lane = tid & 31, warp = tid >> 5;
    int wm = (warp >> 2) * 64, wn = (warp & 3) * 32;
    int g = lane >> 2, t = lane & 3;
    int m0 = blockIdx.y * 128, n0 = blockIdx.x * 128;

    int lrow = tid >> 3, lc8 = (tid & 7) * 8;
    const __half* Ag = A + (size_t)(m0 + lrow) * DD + lc8;
    const __half* Wg = W + (size_t)(n0 + lrow) * DD + lc8;
    uint32_t aS = base + (lrow * GP + lc8) * 2;
    uint32_t bS = base + 2 * ASTB + (lrow * GP + lc8) * 2;
    const uint32_t RG = 32 * GP * 2;
    const size_t   RGg = (size_t)32 * DD;

    int lr = lane & 15, lch = (lane >> 4) * 8;
    int brow = (lane & 7) + ((lane & 16) >> 1);
    int bch = (lane & 8);
    uint32_t aA[4], bA[2];
#pragma unroll
    for (int i = 0; i < 4; i++)
        aA[i] = base + ((wm + i * 16 + lr) * GP + lch) * 2;
#pragma unroll
    for (int jp = 0; jp < 2; jp++)
        bA[jp] = base + 2 * ASTB + ((wn + jp * 16 + brow) * GP + bch) * 2;

    float acc[4][4][4] = {};

#pragma unroll
    for (int rg = 0; rg < 4; rg++) {
        cpa16(aS + rg * RG, Ag + rg * RGg);
        cpa16(bS + rg * RG, Wg + rg * RGg);
    }
    cp_commit();

    const int NKT = DD / 64;
    for (int kt = 0; kt < NKT; kt++) {
        cp_wait<0>();
        __syncthreads();
        if (kt + 1 < NKT) {
            int k0 = (kt + 1) * 64;
            uint32_t sp = ((kt + 1) & 1) * (uint32_t)ASTB;
#pragma unroll
            for (int rg = 0; rg < 4; rg++) {
                cpa16(aS + sp + rg * RG, Ag + rg * RGg + k0);
                cpa16(bS + sp + rg * RG, Wg + rg * RGg + k0);
            }
            cp_commit();
        }
        uint32_t so = (kt & 1) * (uint32_t)ASTB;
#pragma unroll
        for (int kk = 0; kk < 4; kk++) {
            int ko = kk * 32;
            uint32_t af[4][4], bf[4][2];
#pragma unroll
            for (int i = 0; i < 4; i++)
                ldsm4(af[i][0], af[i][1], af[i][2], af[i][3], aA[i] + so + ko);
#pragma unroll
            for (int jp = 0; jp < 2; jp++)
                ldsm4(bf[2*jp][0], bf[2*jp][1], bf[2*jp+1][0], bf[2*jp+1][1],
                      bA[jp] + so + ko);
#pragma unroll
            for (int i = 0; i < 4; i++)
#pragma unroll
                for (int j = 0; j < 4; j++)
                    mma16(acc[i][j], af[i], bf[j]);
        }
    }

    if (MODE == 0) {
        __half* out = (__half*)outv + (size_t)(n0 >> 10) * BTD;
        float qs = (n0 < DD) ? 0.125f : 1.f;
#pragma unroll
        for (int i = 0; i < 4; i++) {
            int row = m0 + wm + i * 16 + g;
            int b = row >> 11, tt = row & 2047;
#pragma unroll
            for (int j = 0; j < 4; j++) {
                int col = (n0 & 1023) + wn + j * 8 + 2 * t;
                int h = col >> 6, d = col & 63;
                __half* d0 = out + (((size_t)(b * HH + h)) * TT + tt) * HD + d;
                __half* d1 = out + (((size_t)(b * HH + h)) * TT + tt + 8) * HD + d;
                *(__half2*)d0 = __floats2half2_rn(acc[i][j][0] * qs, acc[i][j][1] * qs);
                *(__half2*)d1 = __floats2half2_rn(acc[i][j][2] * qs, acc[i][j][3] * qs);
            }
        }
    } else {
        float* out = (float*)outv;
#pragma unroll
        for (int i = 0; i < 4; i++) {
            int row = m0 + wm + i * 16 + g;
#pragma unroll
            for (int j = 0; j < 4; j++) {
                int col = n0 + wn + j * 8 + 2 * t;
                float2 b2 = *(const float2*)(bias + col);
                float2 r0 = *(const float2*)(res + (size_t)row * DD + col);
                float2 r1 = *(const float2*)(res + (size_t)(row + 8) * DD + col);
                *(float2*)(out + (size_t)row * DD + col) =
                    make_float2(acc[i][j][0] + r0.x + b2.x, acc[i][j][1] + r0.y + b2.y);
                *(float2*)(out + (size_t)(row + 8) * DD + col) =
                    make_float2(acc[i][j][2] + r1.x + b2.x, acc[i][j][3] + r1.y + b2.y);
            }
        }
    }
}

// ===========================================================================
// Fused flash attention (fp16 in/out, fp32 accum). Q pre-scaled by 0.125.
// 64 q-rows per CTA, 128 threads (4 warps x 16 rows), static smem, 2-stage
// cp.async, single barrier per kv-tile. Grid (bh, tile) with tiles reversed:
// all bh instances of the heaviest tile launch first (tail-packing).
// Mainloop is maskless; the diagonal tile runs as the final iteration.
// ===========================================================================
__global__ __launch_bounds__(128, 4)
void flash_attn(const __half* __restrict__ Q, const __half* __restrict__ K,
                const __half* __restrict__ V, __half* __restrict__ C) {
    __shared__ __align__(16) __half Ks[2][64 * KP];
    __shared__ __align__(16) __half Vs[2][64 * VP];

    int bh = blockIdx.x;                            // x = bh (fast dim)
    int m0 = (gridDim.y - 1 - blockIdx.y) * 64;     // y = q-tile, heaviest first
    const __half* Qb = Q + (size_t)bh * TT * HD;
    const __half* Kb = K + (size_t)bh * TT * HD;
    const __half* Vb = V + (size_t)bh * TT * HD;

    int tid = threadIdx.x, lane = tid & 31, warp = tid >> 5;
    int wm = warp * 16;
    int g = lane >> 2, t = lane & 3;
    int row0 = m0 + wm + g, row1 = row0 + 8;

    int lrow = tid >> 3, lc8 = (tid & 7) * 8;
    const __half* Kg = Kb + (size_t)lrow * HD + lc8;
    const __half* Vg = Vb + (size_t)lrow * HD + lc8;
    uint32_t kS = s2u(Ks) + (lrow * KP + lc8) * 2;
    uint32_t vS = s2u(Vs) + (lrow * VP + lc8) * 2;
    const uint32_t RGK = 16 * KP * 2, RGV = 16 * VP * 2;
    const size_t RGg = (size_t)16 * HD;

    uint32_t ksb = s2u(Ks), vsb = s2u(Vs);
    int krow = (lane & 7) + ((lane & 16) >> 1);
    int kch = (lane & 8);
    uint32_t kA[4];
#pragma unroll
    for (int jp = 0; jp < 4; jp++)
        kA[jp] = ksb + ((jp * 16 + krow) * KP + kch) * 2;
    uint32_t vA = vsb + (((lane & 7) + (lane & 8)) * VP + ((lane & 16) >> 1)) * 2;

    uint32_t qf[4][4];
#pragma unroll
    for (int ks = 0; ks < 4; ks++) {
        int kb = ks * 16;
        qf[ks][0] = *(const uint32_t*)(Qb + (size_t)row0 * HD + kb + 2 * t);
        qf[ks][1] = *(const uint32_t*)(Qb + (size_t)row1 * HD + kb + 2 * t);
        qf[ks][2] = *(const uint32_t*)(Qb + (size_t)row0 * HD + kb + 8 + 2 * t);
        qf[ks][3] = *(const uint32_t*)(Qb + (size_t)row1 * HD + kb + 8 + 2 * t);
    }

    float o[8][4] = {};
    float sacc[4] = {};
    float rmax0 = -1e30f, rmax1 = -1e30f;
    const uint32_t onef[2] = {ONE2, ONE2};

    int nkv = (m0 + 64) / 64;
#pragma unroll
    for (int rg = 0; rg < 4; rg++) {
        cpa16(kS + rg * RGK, Kg + rg * RGg);
        cpa16(vS + rg * RGV, Vg + rg * RGg);
    }
    cp_commit();

    for (int kv = 0; kv < nkv; kv++) {
        cp_wait<0>();
        __syncthreads();
        if (kv + 1 < nkv) {
            size_t go = (size_t)(kv + 1) * 64 * HD;
            uint32_t sk = ((kv + 1) & 1) * (uint32_t)KSTG;
#pragma unroll
            for (int rg = 0; rg < 4; rg++) {
                cpa16(kS + sk + rg * RGK, Kg + go + rg * RGg);
                cpa16(vS + sk + rg * RGV, Vg + go + rg * RGg);
            }
            cp_commit();
        }
        uint32_t so = (kv & 1) * (uint32_t)KSTG;

        // ---- S = Q @ K^T (16 x 64) ----
        float s[8][4];
#pragma unroll
        for (int j = 0; j < 8; j++) { s[j][0]=0.f; s[j][1]=0.f; s[j][2]=0.f; s[j][3]=0.f; }
#pragma unroll
        for (int ks = 0; ks < 4; ks++) {
            int ko = ks * 32;
            uint32_t kf[8][2];
#pragma unroll
            for (int jp = 0; jp < 4; jp++)
                ldsm4(kf[2*jp][0], kf[2*jp][1], kf[2*jp+1][0], kf[2*jp+1][1],
                      kA[jp] + so + ko);
#pragma unroll
            for (int j = 0; j < 8; j++)
                mma16(s[j], qf[ks], kf[j]);
        }

        // ---- causal mask: only the diagonal (last) tile ----
        if (kv == nkv - 1) {
            int kv0 = kv * 64;
#pragma unroll
            for (int j = 0; j < 8; j++) {
                int c0 = kv0 + j * 8 + 2 * t, c1 = c0 + 1;
                if (c0 > row0) s[j][0] = -1e30f;
                if (c1 > row0) s[j][1] = -1e30f;
                if (c0 > row1) s[j][2] = -1e30f;
                if (c1 > row1) s[j][3] = -1e30f;
            }
        }

        // ---- online softmax: packed half2 quad max (2 shuffles) ----
        float m0l = -1e30f, m1l = -1e30f;
#pragma unroll
        for (int j = 0; j < 8; j++) {
            m0l = fmaxf(m0l, fmaxf(s[j][0], s[j][1]));
            m1l = fmaxf(m1l, fmaxf(s[j][2], s[j][3]));
        }
        uint32_t pm = packh2(m0l, m1l);
        pm = hmax2u(pm, __shfl_xor_sync(FULL, pm, 1));
        pm = hmax2u(pm, __shfl_xor_sync(FULL, pm, 2));
        __half2 mh = *(__half2*)&pm;
        float mf0 = __low2float(mh), mf1 = __high2float(mh);
        float mn0 = fmaxf(rmax0, mf0), mn1 = fmaxf(rmax1, mf1);
        if (mf0 > rmax0 || mf1 > rmax1) {
            float cr0 = __expf(rmax0 - mn0), cr1 = __expf(rmax1 - mn1);
            sacc[0] *= cr0; sacc[1] *= cr0; sacc[2] *= cr1; sacc[3] *= cr1;
#pragma unroll
            for (int j = 0; j < 8; j++) {
                o[j][0] *= cr0; o[j][1] *= cr0; o[j][2] *= cr1; o[j][3] *= cr1;
            }
        }
        rmax0 = mn0; rmax1 = mn1;

        // ---- exp (log2 domain, paired fp16) -> P frags ----
        float b0 = -mn0 * L2E, b1 = -mn1 * L2E;
        uint32_t pan[4][4];
#pragma unroll
        for (int kb2 = 0; kb2 < 4; kb2++) {
            int j0 = 2 * kb2, j1 = 2 * kb2 + 1;
            pan[kb2][0] = ex2h2(packh2(fmaf(s[j0][0], L2E, b0), fmaf(s[j0][1], L2E, b0)));
            pan[kb2][1] = ex2h2(packh2(fmaf(s[j0][2], L2E, b1), fmaf(s[j0][3], L2E, b1)));
            pan[kb2][2] = ex2h2(packh2(fmaf(s[j1][0], L2E, b0), fmaf(s[j1][1], L2E, b0)));
            pan[kb2][3] = ex2h2(packh2(fmaf(s[j1][2], L2E, b1), fmaf(s[j1][3], L2E, b1)));
        }

        // ---- row sums (ones-mma) + O += P @ V ----
#pragma unroll
        for (int kb2 = 0; kb2 < 4; kb2++) {
            mma16(sacc, pan[kb2], onef);
            uint32_t vf[8][2];
#pragma unroll
            for (int jp = 0; jp < 4; jp++)
                ldsm4t(vf[2*jp][0], vf[2*jp][1], vf[2*jp+1][0], vf[2*jp+1][1],
                       vA + so + (kb2 * 16 * VP + jp * 16) * 2);
#pragma unroll
            for (int j = 0; j < 8; j++)
                mma16(o[j], pan[kb2], vf[j]);
        }
    }

    // ---- epilogue ----
    float i0 = 1.f / sacc[0], i1 = 1.f / sacc[2];
    int b = bh >> 4, h = bh & 15;
#pragma unroll
    for (int j = 0; j < 8; j++) {
        int col = j * 8 + 2 * t;
        *(__half2*)(C + ((size_t)(b * TT + row0)) * DD + h * HD + col) =
            __floats2half2_rn(o[j][0] * i0, o[j][1] * i0);
        *(__half2*)(C + ((size_t)(b * TT + row1)) * DD + h * HD + col) =
            __floats2half2_rn(o[j][2] * i1, o[j][3] * i1);
    }
}

// ---------------------------------------------------------------------------
// LayerNorm (faithful bug: scale * x_norm + scale), emits fp16
// ---------------------------------------------------------------------------
__global__ void ln_kernel(const float* __restrict__ x,
                          const float* __restrict__ scale,
                          __half* __restrict__ y) {
    int row = blockIdx.x;
    const float* xr = x + (size_t)row * DD;
    __half* yr = y + (size_t)row * DD;
    int tid = threadIdx.x;
    float v[4];
    float s = 0.f, s2 = 0.f;
#pragma unroll
    for (int i = 0; i < 4; i++) {
        v[i] = xr[tid + 256 * i];
        s  += v[i];
        s2 += v[i] * v[i];
    }
    __shared__ float sh[256], sh2[256];
    sh[tid] = s; sh2[tid] = s2;
    __syncthreads();
    for (int o = 128; o > 0; o >>= 1) {
        if (tid < o) { sh[tid] += sh[tid + o]; sh2[tid] += sh2[tid + o]; }
        __syncthreads();
    }
    float mean = sh[0] * (1.f / DD);
    float var  = sh2[0] * (1.f / DD) - mean * mean;
    float rstd = rsqrtf(var + 1e-5f);
#pragma unroll
    for (int i = 0; i < 4; i++) {
        int c = tid + 256 * i;
        float sc = scale[c];
        yr[c] = __float2half(sc * ((v[i] - mean) * rstd) + sc);
    }
}

// ---------------------------------------------------------------------------
// Host driver
// ---------------------------------------------------------------------------
static void run_block(const float* x_in, const float* ln_scale,
                      const __half* wqkv, const __half* wo, const float* bo,
                      __half* lnp, __half* qkvp, __half* ctxp, float* out) {
    ln_kernel<<<BB * TT, 256>>>(x_in, ln_scale, lnp);
    mma_gemm<0><<<dim3(3 * DD / 128, (BB * TT) / 128), 256, GSMEM>>>(
        lnp, wqkv, nullptr, nullptr, qkvp);
    flash_attn<<<dim3(BB * HH, TT / 64), 128>>>(
        qkvp, qkvp + BTD, qkvp + 2 * BTD, ctxp);
    mma_gemm<1><<<dim3(DD / 128, (BB * TT) / 128), 256, GSMEM>>>(
        ctxp, wo, bo, x_in, out);
}

extern "C" void kernel_launch(void* const* d_in, const int* in_sizes, int n_in,
                              void* d_out, int out_size) {
    const float* x   = (const float*)d_in[0];
    const float* bo  = (const float*)d_in[5];
    const float* ln1 = (const float*)d_in[6];
    const float* ln2 = (const float*)d_in[7];
    float* out = (float*)d_out;

    static bool init_done = false;
    static cudaStream_t s1;
    static cudaEvent_t ev_fork, ev_join;
    if (!init_done) {
        cudaFuncSetAttribute(mma_gemm<0>, cudaFuncAttributeMaxDynamicSharedMemorySize, GSMEM);
        cudaFuncSetAttribute(mma_gemm<1>, cudaFuncAttributeMaxDynamicSharedMemorySize, GSMEM);
        cudaStreamCreateWithFlags(&s1, cudaStreamNonBlocking);
        cudaEventCreateWithFlags(&ev_fork, cudaEventDisableTiming);
        cudaEventCreateWithFlags(&ev_join, cudaEventDisableTiming);
        init_done = true;
    }

    __half *lnp, *qkvp, *ctxp, *wt;
    float* hp;
    cudaGetSymbolAddress((void**)&lnp,  g_ln);
    cudaGetSymbolAddress((void**)&qkvp, g_qkv);
    cudaGetSymbolAddress((void**)&ctxp, g_ctx);
    cudaGetSymbolAddress((void**)&hp,   g_h);
    cudaGetSymbolAddress((void**)&wt,   g_w);

    // fork: weight conversion runs concurrently with block-1 LayerNorm
    cudaEventRecord(ev_fork, 0);
    cudaStreamWaitEvent(s1, ev_fork, 0);
    cvt_h4<<<dim3((DD * DD / 4) / 256, 4), 256, 0, s1>>>(
        (const float4*)d_in[1], (const float4*)d_in[2],
        (const float4*)d_in[3], (const float4*)d_in[4], (__half2*)wt);
    cudaEventRecord(ev_join, s1);

    const __half* wqkv = wt;
    const __half* wo   = wt + (size_t)3 * DD * DD;

    // block 1 LN on the main stream (parallel with cvt), then join before QKV
    ln_kernel<<<BB * TT, 256>>>(x, ln1, lnp);
    cudaStreamWaitEvent(0, ev_join, 0);
    mma_gemm<0><<<dim3(3 * DD / 128, (BB * TT) / 128), 256, GSMEM>>>(
        lnp, wqkv, nullptr, nullptr, qkvp);
    flash_attn<<<dim3(BB * HH, TT / 64), 128>>>(
        qkvp, qkvp + BTD, qkvp + 2 * BTD, ctxp);
    mma_gemm<1><<<dim3(DD / 128, (BB * TT) / 128), 256, GSMEM>>>(
        ctxp, wo, bo, x, hp);

    // block 2
    run_block(hp, ln2, wqkv, wo, bo, lnp, qkvp, ctxp, out);
}